// round 13
// baseline (speedup 1.0000x reference)
#include <cuda_runtime.h>
#include <cuda_fp16.h>
#include <stdint.h>

#define BATCH 16
#define SEQ   2048
#define DIM   128
#define NT    256          // attn threads
#define NTH   320          // + 2 converter warps
#define KTILES 32
#define NQT   256          // 16 batches x 16 q-tiles
#define GRID  148

// smem: 4 stages x 32KB = 128KB, then converter scratch / bcast words / meanV
#define STAGE_B  32768u
#define SCR_OFF  131072
#define CW_OFF   133120
#define QW_OFF   133152
#define MV_OFF   133184
#define SMEM_BYTES 133696

__device__ uint2 g_K16[BATCH * SEQ * DIM / 4];
__device__ uint2 g_V16[BATCH * SEQ * DIM / 4];
__device__ float g_vpart[BATCH][KTILES][DIM];
__device__ int   g_flags[BATCH * KTILES];
__device__ int   g_cnt, g_q1, g_q2;

// ---------------------------------------------------------------------------
__global__ void reset_kernel() {
    int i = threadIdx.x;
    if (i < BATCH * KTILES) g_flags[i] = 0;
    if (i == 0) { g_cnt = 0; g_q1 = 0; g_q2 = 0; }
}

// ---------------------------------------------------------------------------
__device__ __forceinline__ float ex2(float x) {
    float y;
    asm("ex2.approx.f32 %0, %1;" : "=f"(y) : "f"(x));
    return y;
}
__device__ __forceinline__ uint32_t smem_u32(const void* p) {
    uint32_t a;
    asm("{ .reg .u64 t; cvta.to.shared.u64 t, %1; cvt.u32.u64 %0, t; }" : "=r"(a) : "l"(p));
    return a;
}
__device__ __forceinline__ void cp16(uint32_t dst, const void* src) {
    asm volatile("cp.async.cg.shared.global [%0], [%1], 16;" :: "r"(dst), "l"(src));
}
__device__ __forceinline__ uint32_t pkh(float lo, float hi) {
    uint32_t r;
    asm("cvt.rn.f16x2.f32 %0, %1, %2;" : "=r"(r) : "f"(hi), "f"(lo));
    return r;
}
__device__ __forceinline__ void mma16(float* c, const uint32_t* a, uint32_t b0, uint32_t b1) {
    asm volatile(
        "mma.sync.aligned.m16n8k16.row.col.f32.f16.f16.f32 "
        "{%0,%1,%2,%3}, {%4,%5,%6,%7}, {%8,%9}, {%0,%1,%2,%3};"
        : "+f"(c[0]), "+f"(c[1]), "+f"(c[2]), "+f"(c[3])
        : "r"(a[0]), "r"(a[1]), "r"(a[2]), "r"(a[3]), "r"(b0), "r"(b1));
}
__device__ __forceinline__ void ldsm4(uint32_t* r, uint32_t a) {
    asm volatile("ldmatrix.sync.aligned.m8n8.x4.shared.b16 {%0,%1,%2,%3}, [%4];"
        : "=r"(r[0]), "=r"(r[1]), "=r"(r[2]), "=r"(r[3]) : "r"(a));
}
__device__ __forceinline__ void ldsm4t(uint32_t* r, uint32_t a) {
    asm volatile("ldmatrix.sync.aligned.m8n8.x4.trans.shared.b16 {%0,%1,%2,%3}, [%4];"
        : "=r"(r[0]), "=r"(r[1]), "=r"(r[2]), "=r"(r[3]) : "r"(a));
}
#define BAR1() asm volatile("bar.sync 1, 256;" ::: "memory")
#define BAR2() asm volatile("bar.sync 2, 64;"  ::: "memory")

// ---------------------------------------------------------------------------
// Fused persistent kernel. Warps 0-7: attention (work-steal q-tiles).
// Warps 8-9: convert K/V fp32->fp16 (work-steal (kt,b) chunks, kt-major),
//            then write masked q-tiles' meanV output.
// ---------------------------------------------------------------------------
__global__ __launch_bounds__(NTH, 1)
void fused_kernel(const float* __restrict__ Qg, const float* __restrict__ Kg,
                  const float* __restrict__ Vg, const int* __restrict__ vlg,
                  float* __restrict__ Og)
{
    extern __shared__ char smem[];
    const int tid = threadIdx.x;
    const int w   = tid >> 5;
    volatile int* vflags = (volatile int*)g_flags;

    // ======================= converter warps =======================
    if (w >= 8) {
        const int ct = tid - 256;                 // 0..63
        float* scr = (float*)(smem + SCR_OFF);
        volatile int* cw = (volatile int*)(smem + CW_OFF);

        // ---- phase 1: convert chunks (chunk = kt*16 + b; 64 keys each) ----
        for (;;) {
            if (ct == 0) *cw = atomicAdd(&g_cnt, 1);
            BAR2();
            int c = *cw;
            BAR2();
            if (c >= BATCH * KTILES) break;
            int kt = c >> 4, b = c & 15;
            size_t fbase = ((size_t)b * SEQ + (size_t)kt * 64) * DIM;
            const float4* k4 = (const float4*)(Kg + fbase);
            const float4* v4 = (const float4*)(Vg + fbase);
            uint4* ko = (uint4*)((uint8_t*)g_K16 + fbase * 2);
            uint4* vo = (uint4*)((uint8_t*)g_V16 + fbase * 2);
            float vs[8];
            #pragma unroll
            for (int j = 0; j < 8; ++j) vs[j] = 0.f;
            #pragma unroll 4
            for (int j = 0; j < 16; ++j) {
                int idx = j * 64 + ct;            // uint4 index; row=idx/16, dchunk=ct&15
                float4 a0 = k4[idx * 2], a1 = k4[idx * 2 + 1];
                float4 b0 = v4[idx * 2], b1 = v4[idx * 2 + 1];
                ko[idx] = make_uint4(pkh(a0.x, a0.y), pkh(a0.z, a0.w),
                                     pkh(a1.x, a1.y), pkh(a1.z, a1.w));
                vo[idx] = make_uint4(pkh(b0.x, b0.y), pkh(b0.z, b0.w),
                                     pkh(b1.x, b1.y), pkh(b1.z, b1.w));
                vs[0] += b0.x; vs[1] += b0.y; vs[2] += b0.z; vs[3] += b0.w;
                vs[4] += b1.x; vs[5] += b1.y; vs[6] += b1.z; vs[7] += b1.w;
            }
            #pragma unroll
            for (int j = 0; j < 8; ++j) scr[ct * 8 + j] = vs[j];
            BAR2();
            if (ct < 16) {                        // fixed-order reduction (deterministic)
                #pragma unroll
                for (int j = 0; j < 8; ++j) {
                    float s = (scr[ct * 8 + j] + scr[(16 + ct) * 8 + j]) +
                              (scr[(32 + ct) * 8 + j] + scr[(48 + ct) * 8 + j]);
                    g_vpart[b][kt][ct * 8 + j] = s;
                }
            }
            BAR2();
            if (ct == 0) { __threadfence(); vflags[b * KTILES + kt] = 1; }
        }

        // ---- phase 2: masked q-tiles -> meanV rows ----
        for (;;) {
            if (ct == 0) *cw = atomicAdd(&g_q2, 1);
            BAR2();
            int q = *cw;
            BAR2();
            if (q >= NQT) break;
            int b = q & 15, q0 = (q >> 4) * 128;
            if (q0 < vlg[b]) continue;
            if (ct == 0) {
                #pragma unroll 1
                for (int i = 0; i < KTILES; ++i) while (vflags[b * KTILES + i] == 0) {}
                __threadfence();
            }
            BAR2();
            float m0 = 0.f, m1 = 0.f;
            #pragma unroll
            for (int i = 0; i < KTILES; ++i) {
                m0 += g_vpart[b][i][2 * ct];
                m1 += g_vpart[b][i][2 * ct + 1];
            }
            scr[2 * ct]     = m0 * (1.0f / SEQ);
            scr[2 * ct + 1] = m1 * (1.0f / SEQ);
            BAR2();
            const float4* mv4 = (const float4*)scr;
            #pragma unroll
            for (int rr = 0; rr < 2; ++rr) {
                int row = q0 + ct + rr * 64;
                float4* o4 = (float4*)(Og + ((size_t)b * SEQ + row) * DIM);
                #pragma unroll
                for (int c4 = 0; c4 < 32; ++c4) o4[c4] = mv4[c4];
            }
        }
        return;
    }

    // ======================= attention warps =======================
    const int lane = tid & 31;
    const int qr   = lane >> 2;
    const int qc   = lane & 3;
    const uint32_t sbase = smem_u32(smem);
    volatile int* qw = (volatile int*)(smem + QW_OFF);

    const uint32_t csrc = (uint32_t)(tid & 15) * 16u;
    const uint32_t r0t  = (uint32_t)(tid >> 4);
    const uint32_t swz  = (uint32_t)((tid & 15) ^ (int)(r0t & 7)) << 4;
    const uint32_t r7 = (uint32_t)(lane & 7);
    const int      lt = lane >> 3;
    const uint32_t kL = sbase + r7 * 256u;
    const uint32_t vL = sbase + 16384u + (uint32_t)(8 * (lt & 1)) * 256u + r7 * 256u;
    const float qscale = 0.088388347648318447f * 1.4426950408889634f;

    for (;;) {
        asm volatile("cp.async.wait_group 0;" ::: "memory");   // drain before stage reuse
        if (tid == 0) *qw = atomicAdd(&g_q1, 1);
        BAR1();
        int q = *qw;
        BAR1();
        if (q >= NQT) break;
        const int b  = q & 15;
        const int q0 = (q >> 4) * 128;
        const int vl = vlg[b];
        if (q0 >= vl) continue;                   // masked: converter warps write it
        const int fb = b * KTILES;
        const uint8_t* kb16 = (const uint8_t*)g_K16 + (size_t)b * SEQ * DIM * 2;
        const uint8_t* vb16 = (const uint8_t*)g_V16 + (size_t)b * SEQ * DIM * 2;

        // ---- gate on tiles 0..2, prefetch flag 3 ----
        int pfv = 1;
        if (tid == 0) {
            while (vflags[fb + 0] == 0) {}
            while (vflags[fb + 1] == 0) {}
            while (vflags[fb + 2] == 0) {}
            pfv = vflags[fb + 3];
            __threadfence();
        }
        BAR1();

        // ---- prologue: stream tiles 0..2 ----
        #pragma unroll
        for (int t = 0; t < 3; ++t) {
            const uint8_t* ks = kb16 + (size_t)t * 16384;
            const uint8_t* vs = vb16 + (size_t)t * 16384;
            uint32_t stg = (uint32_t)t * STAGE_B;
            #pragma unroll
            for (int i = 0; i < 4; ++i) {
                uint32_t r = (uint32_t)i * 16u + r0t;
                cp16(sbase + stg + r * 256u + swz, ks + r * 256u + csrc);
                cp16(sbase + stg + 16384u + r * 256u + swz, vs + r * 256u + csrc);
            }
            asm volatile("cp.async.commit_group;");
        }

        const bool active = (q0 + w * 16) < vl;   // warp has at least one live row

        // ---- Q A-frags (fp16, scaled) ----
        uint32_t qa[8][4];
        if (active) {
            const float* r0 = Qg + ((size_t)b * SEQ + q0 + w * 16 + qr) * DIM;
            const float* r1 = r0 + 8 * DIM;
            #pragma unroll
            for (int kb = 0; kb < 8; ++kb) {
                int d0 = kb * 16 + 2 * qc;
                float2 a = *(const float2*)(r0 + d0);
                float2 c = *(const float2*)(r1 + d0);
                float2 e = *(const float2*)(r0 + d0 + 8);
                float2 f = *(const float2*)(r1 + d0 + 8);
                qa[kb][0] = pkh(a.x * qscale, a.y * qscale);
                qa[kb][1] = pkh(c.x * qscale, c.y * qscale);
                qa[kb][2] = pkh(e.x * qscale, e.y * qscale);
                qa[kb][3] = pkh(f.x * qscale, f.y * qscale);
            }
        }

        float o[16][4];
        #pragma unroll
        for (int n = 0; n < 16; ++n) { o[n][0] = o[n][1] = o[n][2] = o[n][3] = 0.f; }
        float l0 = 0.f, l1 = 0.f;

        for (int kt = 0; kt < KTILES; ++kt) {
            asm volatile("cp.async.wait_group 2;" ::: "memory");
            if (tid == 0) {
                if (kt + 3 < KTILES && pfv == 0) {
                    while (vflags[fb + kt + 3] == 0) {}
                }
                __threadfence();
            }
            BAR1();

            if (kt + 3 < KTILES) {
                const uint32_t nb = (uint32_t)((kt + 3) & 3) * STAGE_B;
                const uint8_t* ks = kb16 + (size_t)(kt + 3) * 16384;
                const uint8_t* vs = vb16 + (size_t)(kt + 3) * 16384;
                #pragma unroll
                for (int i = 0; i < 4; ++i) {
                    uint32_t r = (uint32_t)i * 16u + r0t;
                    cp16(sbase + nb + r * 256u + swz, ks + r * 256u + csrc);
                    cp16(sbase + nb + 16384u + r * 256u + swz, vs + r * 256u + csrc);
                }
            }
            asm volatile("cp.async.commit_group;");
            if (tid == 0) pfv = (kt + 4 < KTILES) ? vflags[fb + kt + 4] : 1;

            if (!active) continue;
            const uint32_t stg = (uint32_t)(kt & 3) * STAGE_B;

            // ---- S = Q * K^T (fp32 accum) ----
            float sacc[8][4];
            #pragma unroll
            for (int n = 0; n < 8; ++n) { sacc[n][0] = sacc[n][1] = sacc[n][2] = sacc[n][3] = 0.f; }
            #pragma unroll
            for (int nb = 0; nb < 8; ++nb) {
                uint32_t abase = kL + stg + (uint32_t)(nb * 8) * 256u;
                #pragma unroll
                for (int g = 0; g < 4; ++g) {
                    uint32_t r[4];
                    ldsm4(r, abase + ((((uint32_t)(4 * g + lt)) ^ r7) << 4));
                    mma16(sacc[nb], qa[2 * g],     r[0], r[1]);
                    mma16(sacc[nb], qa[2 * g + 1], r[2], r[3]);
                }
            }

            // ---- softmax (no max) + P into A-frags ----
            uint32_t pa[4][4];
            #pragma unroll
            for (int kb = 0; kb < 4; ++kb) {
                float e00 = ex2(sacc[2 * kb][0]),     e01 = ex2(sacc[2 * kb][1]);
                float e02 = ex2(sacc[2 * kb][2]),     e03 = ex2(sacc[2 * kb][3]);
                float e10 = ex2(sacc[2 * kb + 1][0]), e11 = ex2(sacc[2 * kb + 1][1]);
                float e12 = ex2(sacc[2 * kb + 1][2]), e13 = ex2(sacc[2 * kb + 1][3]);
                l0 += (e00 + e01) + (e10 + e11);
                l1 += (e02 + e03) + (e12 + e13);
                pa[kb][0] = pkh(e00, e01);
                pa[kb][1] = pkh(e02, e03);
                pa[kb][2] = pkh(e10, e11);
                pa[kb][3] = pkh(e12, e13);
            }

            // ---- O += P * V (fp32 accum) ----
            #pragma unroll
            for (int np = 0; np < 8; ++np) {
                uint32_t coff = (((uint32_t)(2 * np + (lt >> 1))) ^ r7) << 4;
                #pragma unroll
                for (int kb = 0; kb < 4; ++kb) {
                    uint32_t r[4];
                    ldsm4t(r, vL + stg + (uint32_t)kb * 4096u + coff);
                    mma16(o[2 * np],     pa[kb], r[0], r[1]);
                    mma16(o[2 * np + 1], pa[kb], r[2], r[3]);
                }
            }
        }

        // ---- epilogue ----
        l0 += __shfl_xor_sync(0xffffffffu, l0, 1);
        l0 += __shfl_xor_sync(0xffffffffu, l0, 2);
        l1 += __shfl_xor_sync(0xffffffffu, l1, 1);
        l1 += __shfl_xor_sync(0xffffffffu, l1, 2);

        float* mvs = (float*)(smem + MV_OFF);
        const bool boundary = vl < q0 + 128;
        if (boundary) {                           // uniform across CTA
            if (tid == 0) {
                #pragma unroll 1
                for (int i = 0; i < KTILES; ++i) while (vflags[fb + i] == 0) {}
                __threadfence();
            }
            BAR1();
            if (tid < 128) {
                float s = 0.f;
                #pragma unroll
                for (int i = 0; i < KTILES; ++i) s += g_vpart[b][i][tid];
                mvs[tid] = s * (1.0f / SEQ);
            }
            BAR1();
        }

        const float inv0 = 1.0f / l0;
        const float inv1 = 1.0f / l1;
        const int row0 = q0 + w * 16 + qr;
        const int row1 = row0 + 8;
        float* O0 = Og + ((size_t)b * SEQ + row0) * DIM;
        float* O1 = Og + ((size_t)b * SEQ + row1) * DIM;
        const bool m0 = row0 >= vl;
        const bool m1 = row1 >= vl;
        #pragma unroll
        for (int n = 0; n < 16; ++n) {
            int col = n * 8 + 2 * qc;
            float2 a0 = m0 ? *(const float2*)&mvs[col]
                           : make_float2(o[n][0] * inv0, o[n][1] * inv0);
            float2 a1 = m1 ? *(const float2*)&mvs[col]
                           : make_float2(o[n][2] * inv1, o[n][3] * inv1);
            *(float2*)(O0 + col) = a0;
            *(float2*)(O1 + col) = a1;
        }
    }
}

extern "C" void kernel_launch(void* const* d_in, const int* in_sizes, int n_in,
                              void* d_out, int out_size) {
    const float* Q  = (const float*)d_in[0];
    const float* K  = (const float*)d_in[1];
    const float* V  = (const float*)d_in[2];
    const int*   vl = (const int*)d_in[3];
    float* out = (float*)d_out;

    reset_kernel<<<1, 512>>>();

    cudaFuncSetAttribute(fused_kernel, cudaFuncAttributeMaxDynamicSharedMemorySize, SMEM_BYTES);
    fused_kernel<<<GRID, NTH, SMEM_BYTES>>>(Q, K, V, vl, out);
}

// round 14
// speedup vs baseline: 1.2015x; 1.2015x over previous
#include <cuda_runtime.h>
#include <cuda_fp16.h>
#include <stdint.h>

#define BATCH 16
#define SEQ   2048
#define DIM   128
#define NT    256
#define KTILES 32
#define NQT   256
#define GRID  148

// smem: 4 stages x [K16 16KB | V16 16KB] = 128KB + claim word
#define STAGE_B    32768u
#define QW_OFF     131072
#define SMEM_BYTES 131104

__device__ uint2 g_K16[BATCH * SEQ * DIM / 4];
__device__ uint2 g_V16[BATCH * SEQ * DIM / 4];
__device__ float g_meanV[BATCH][DIM];
__device__ float g_part[64][BATCH][DIM];
__device__ int   g_q1;

// ---------------------------------------------------------------------------
// helpers
// ---------------------------------------------------------------------------
__device__ __forceinline__ float ex2(float x) {
    float y;
    asm("ex2.approx.f32 %0, %1;" : "=f"(y) : "f"(x));
    return y;
}
__device__ __forceinline__ uint32_t smem_u32(const void* p) {
    uint32_t a;
    asm("{ .reg .u64 t; cvta.to.shared.u64 t, %1; cvt.u32.u64 %0, t; }" : "=r"(a) : "l"(p));
    return a;
}
__device__ __forceinline__ void cp16(uint32_t dst, const void* src) {
    asm volatile("cp.async.cg.shared.global [%0], [%1], 16;" :: "r"(dst), "l"(src));
}
__device__ __forceinline__ uint32_t pkh(float lo, float hi) {
    uint32_t r;
    asm("cvt.rn.f16x2.f32 %0, %1, %2;" : "=r"(r) : "f"(hi), "f"(lo));
    return r;
}
__device__ __forceinline__ void mma16(float* c, const uint32_t* a, uint32_t b0, uint32_t b1) {
    asm volatile(
        "mma.sync.aligned.m16n8k16.row.col.f32.f16.f16.f32 "
        "{%0,%1,%2,%3}, {%4,%5,%6,%7}, {%8,%9}, {%0,%1,%2,%3};"
        : "+f"(c[0]), "+f"(c[1]), "+f"(c[2]), "+f"(c[3])
        : "r"(a[0]), "r"(a[1]), "r"(a[2]), "r"(a[3]), "r"(b0), "r"(b1));
}
__device__ __forceinline__ void ldsm4(uint32_t* r, uint32_t a) {
    asm volatile("ldmatrix.sync.aligned.m8n8.x4.shared.b16 {%0,%1,%2,%3}, [%4];"
        : "=r"(r[0]), "=r"(r[1]), "=r"(r[2]), "=r"(r[3]) : "r"(a));
}
__device__ __forceinline__ void ldsm4t(uint32_t* r, uint32_t a) {
    asm volatile("ldmatrix.sync.aligned.m8n8.x4.trans.shared.b16 {%0,%1,%2,%3}, [%4];"
        : "=r"(r[0]), "=r"(r[1]), "=r"(r[2]), "=r"(r[3]) : "r"(a));
}

// ---------------------------------------------------------------------------
// cvt_kernel: K,V fp32 -> fp16 (16B stores) + V column-sum partials. 1024 CTAs.
// ---------------------------------------------------------------------------
__global__ void cvt_kernel(const float* __restrict__ K, const float* __restrict__ V) {
    __shared__ float red[NT * 8];
    const int tid = threadIdx.x;
    const int b   = blockIdx.x >> 6;
    const int sl  = blockIdx.x & 63;
    const size_t fbase = ((size_t)b * SEQ + (size_t)sl * 32) * DIM;
    const float4* k4 = (const float4*)(K + fbase);
    const float4* v4 = (const float4*)(V + fbase);
    uint4* ko = (uint4*)(g_K16 + fbase / 4);
    uint4* vo = (uint4*)(g_V16 + fbase / 4);

    float4 ka[4], va[4];
    #pragma unroll
    for (int i = 0; i < 2; ++i) {
        int t8 = i * NT + tid;
        ka[2*i]   = k4[t8 * 2];
        ka[2*i+1] = k4[t8 * 2 + 1];
        va[2*i]   = v4[t8 * 2];
        va[2*i+1] = v4[t8 * 2 + 1];
    }
    float vs[8];
    #pragma unroll
    for (int j = 0; j < 8; ++j) vs[j] = 0.f;
    #pragma unroll
    for (int i = 0; i < 2; ++i) {
        int t8 = i * NT + tid;
        ko[t8] = make_uint4(pkh(ka[2*i].x, ka[2*i].y),   pkh(ka[2*i].z, ka[2*i].w),
                            pkh(ka[2*i+1].x, ka[2*i+1].y), pkh(ka[2*i+1].z, ka[2*i+1].w));
        vo[t8] = make_uint4(pkh(va[2*i].x, va[2*i].y),   pkh(va[2*i].z, va[2*i].w),
                            pkh(va[2*i+1].x, va[2*i+1].y), pkh(va[2*i+1].z, va[2*i+1].w));
        vs[0] += va[2*i].x; vs[1] += va[2*i].y; vs[2] += va[2*i].z; vs[3] += va[2*i].w;
        vs[4] += va[2*i+1].x; vs[5] += va[2*i+1].y; vs[6] += va[2*i+1].z; vs[7] += va[2*i+1].w;
    }
    #pragma unroll
    for (int j = 0; j < 8; ++j) red[tid * 8 + j] = vs[j];
    __syncthreads();
    if (tid < 16) {
        float s[8];
        #pragma unroll
        for (int j = 0; j < 8; ++j) s[j] = 0.f;
        #pragma unroll
        for (int g = 0; g < 16; ++g)
            #pragma unroll
            for (int j = 0; j < 8; ++j) s[j] += red[(g * 16 + tid) * 8 + j];
        #pragma unroll
        for (int j = 0; j < 8; ++j) g_part[sl][b][tid * 8 + j] = s[j];
    }
}

__global__ void meanv_final() {
    int b = blockIdx.x;
    int d = threadIdx.x;
    float s = 0.f;
    #pragma unroll
    for (int i = 0; i < 64; ++i) s += g_part[i][b][d];
    g_meanV[b][d] = s * (1.0f / SEQ);
    if (b == 0 && d == 0) g_q1 = 0;       // reset work counter for attn
}

// ---------------------------------------------------------------------------
// Persistent flash attention: 148 CTAs work-steal q-tiles (one atomic/q-tile).
// Heavy tile body identical to the round-11 loop (4-stage cp.async, fp16 mma,
// fp32 accum, P in registers, no online max). Masked q-tiles written inline.
// ---------------------------------------------------------------------------
__global__ __launch_bounds__(NT, 1)
void attn_kernel(const float* __restrict__ Qg, const int* __restrict__ vlg,
                 float* __restrict__ Og)
{
    extern __shared__ char smem[];
    const int tid  = threadIdx.x;
    const int lane = tid & 31;
    const int w    = tid >> 5;
    const int qr   = lane >> 2;
    const int qc   = lane & 3;
    const uint32_t sbase = smem_u32(smem);
    volatile int* qw = (volatile int*)(smem + QW_OFF);

    const uint32_t csrc = (uint32_t)(tid & 15) * 16u;
    const uint32_t r0t  = (uint32_t)(tid >> 4);
    const uint32_t swz  = (uint32_t)((tid & 15) ^ (int)(r0t & 7)) << 4;
    const uint32_t r7 = (uint32_t)(lane & 7);
    const int      lt = lane >> 3;
    const uint32_t kL = sbase + r7 * 256u;
    const uint32_t vL = sbase + 16384u + (uint32_t)(8 * (lt & 1)) * 256u + r7 * 256u;
    const float qscale = 0.088388347648318447f * 1.4426950408889634f;

    for (;;) {
        if (tid == 0) *qw = atomicAdd(&g_q1, 1);
        __syncthreads();
        const int q = *qw;
        __syncthreads();
        if (q >= NQT) break;

        const int b  = q & 15;
        const int q0 = (q >> 4) * 128;
        const int vl = vlg[b];

        // ---- masked q-tile: write meanV rows, keep stealing ----
        if (q0 >= vl) {
            int row = tid >> 1, hh = tid & 1;
            const float4* mv = (const float4*)&g_meanV[b][hh * 64];
            float4* o4 = (float4*)(Og + ((size_t)b * SEQ + q0 + row) * DIM + hh * 64);
            #pragma unroll
            for (int j = 0; j < 16; ++j) o4[j] = mv[j];
            continue;
        }

        // ---- heavy q-tile ----
        asm volatile("cp.async.wait_group 0;" ::: "memory");   // drain prior tile's groups

        const uint8_t* kb16 = (const uint8_t*)g_K16 + (size_t)b * SEQ * DIM * 2;
        const uint8_t* vb16 = (const uint8_t*)g_V16 + (size_t)b * SEQ * DIM * 2;

        #pragma unroll
        for (int t = 0; t < 3; ++t) {
            const uint8_t* ks = kb16 + (size_t)t * 16384;
            const uint8_t* vs = vb16 + (size_t)t * 16384;
            uint32_t stg = (uint32_t)t * STAGE_B;
            #pragma unroll
            for (int i = 0; i < 4; ++i) {
                uint32_t r = (uint32_t)i * 16u + r0t;
                cp16(sbase + stg + r * 256u + swz, ks + r * 256u + csrc);
                cp16(sbase + stg + 16384u + r * 256u + swz, vs + r * 256u + csrc);
            }
            asm volatile("cp.async.commit_group;");
        }

        // Q A-frags (fp16, scaled)
        uint32_t qa[8][4];
        {
            const float* r0 = Qg + ((size_t)b * SEQ + q0 + w * 16 + qr) * DIM;
            const float* r1 = r0 + 8 * DIM;
            #pragma unroll
            for (int kb = 0; kb < 8; ++kb) {
                int d0 = kb * 16 + 2 * qc;
                float2 a = *(const float2*)(r0 + d0);
                float2 c = *(const float2*)(r1 + d0);
                float2 e = *(const float2*)(r0 + d0 + 8);
                float2 f = *(const float2*)(r1 + d0 + 8);
                qa[kb][0] = pkh(a.x * qscale, a.y * qscale);
                qa[kb][1] = pkh(c.x * qscale, c.y * qscale);
                qa[kb][2] = pkh(e.x * qscale, e.y * qscale);
                qa[kb][3] = pkh(f.x * qscale, f.y * qscale);
            }
        }

        float o[16][4];
        #pragma unroll
        for (int n = 0; n < 16; ++n) { o[n][0] = o[n][1] = o[n][2] = o[n][3] = 0.f; }
        float l0 = 0.f, l1 = 0.f;

        for (int kt = 0; kt < KTILES; ++kt) {
            asm volatile("cp.async.wait_group 2;" ::: "memory");
            __syncthreads();

            if (kt + 3 < KTILES) {
                const uint32_t nb = (uint32_t)((kt + 3) & 3) * STAGE_B;
                const uint8_t* ks = kb16 + (size_t)(kt + 3) * 16384;
                const uint8_t* vs = vb16 + (size_t)(kt + 3) * 16384;
                #pragma unroll
                for (int i = 0; i < 4; ++i) {
                    uint32_t r = (uint32_t)i * 16u + r0t;
                    cp16(sbase + nb + r * 256u + swz, ks + r * 256u + csrc);
                    cp16(sbase + nb + 16384u + r * 256u + swz, vs + r * 256u + csrc);
                }
            }
            asm volatile("cp.async.commit_group;");

            const uint32_t stg = (uint32_t)(kt & 3) * STAGE_B;

            // S = Q * K^T (fp32 accum)
            float sacc[8][4];
            #pragma unroll
            for (int n = 0; n < 8; ++n) { sacc[n][0] = sacc[n][1] = sacc[n][2] = sacc[n][3] = 0.f; }
            #pragma unroll
            for (int nb = 0; nb < 8; ++nb) {
                uint32_t abase = kL + stg + (uint32_t)(nb * 8) * 256u;
                #pragma unroll
                for (int g = 0; g < 4; ++g) {
                    uint32_t r[4];
                    ldsm4(r, abase + ((((uint32_t)(4 * g + lt)) ^ r7) << 4));
                    mma16(sacc[nb], qa[2 * g],     r[0], r[1]);
                    mma16(sacc[nb], qa[2 * g + 1], r[2], r[3]);
                }
            }

            // softmax (no max) + P into A-frags
            uint32_t pa[4][4];
            #pragma unroll
            for (int kb = 0; kb < 4; ++kb) {
                float e00 = ex2(sacc[2 * kb][0]),     e01 = ex2(sacc[2 * kb][1]);
                float e02 = ex2(sacc[2 * kb][2]),     e03 = ex2(sacc[2 * kb][3]);
                float e10 = ex2(sacc[2 * kb + 1][0]), e11 = ex2(sacc[2 * kb + 1][1]);
                float e12 = ex2(sacc[2 * kb + 1][2]), e13 = ex2(sacc[2 * kb + 1][3]);
                l0 += (e00 + e01) + (e10 + e11);
                l1 += (e02 + e03) + (e12 + e13);
                pa[kb][0] = pkh(e00, e01);
                pa[kb][1] = pkh(e02, e03);
                pa[kb][2] = pkh(e10, e11);
                pa[kb][3] = pkh(e12, e13);
            }

            // O += P * V (fp32 accum)
            #pragma unroll
            for (int np = 0; np < 8; ++np) {
                uint32_t coff = (((uint32_t)(2 * np + (lt >> 1))) ^ r7) << 4;
                #pragma unroll
                for (int kb = 0; kb < 4; ++kb) {
                    uint32_t r[4];
                    ldsm4t(r, vL + stg + (uint32_t)kb * 4096u + coff);
                    mma16(o[2 * np],     pa[kb], r[0], r[1]);
                    mma16(o[2 * np + 1], pa[kb], r[2], r[3]);
                }
            }
        }

        // epilogue
        l0 += __shfl_xor_sync(0xffffffffu, l0, 1);
        l0 += __shfl_xor_sync(0xffffffffu, l0, 2);
        l1 += __shfl_xor_sync(0xffffffffu, l1, 1);
        l1 += __shfl_xor_sync(0xffffffffu, l1, 2);

        const float inv0 = 1.0f / l0;
        const float inv1 = 1.0f / l1;
        const int row0 = q0 + w * 16 + qr;
        const int row1 = row0 + 8;
        float* O0 = Og + ((size_t)b * SEQ + row0) * DIM;
        float* O1 = Og + ((size_t)b * SEQ + row1) * DIM;
        const bool m0 = row0 >= vl;
        const bool m1 = row1 >= vl;
        #pragma unroll
        for (int n = 0; n < 16; ++n) {
            int col = n * 8 + 2 * qc;
            float2 a0 = m0 ? *(const float2*)&g_meanV[b][col]
                           : make_float2(o[n][0] * inv0, o[n][1] * inv0);
            float2 a1 = m1 ? *(const float2*)&g_meanV[b][col]
                           : make_float2(o[n][2] * inv1, o[n][3] * inv1);
            *(float2*)(O0 + col) = a0;
            *(float2*)(O1 + col) = a1;
        }
    }
}

extern "C" void kernel_launch(void* const* d_in, const int* in_sizes, int n_in,
                              void* d_out, int out_size) {
    const float* Q  = (const float*)d_in[0];
    const float* K  = (const float*)d_in[1];
    const float* V  = (const float*)d_in[2];
    const int*   vl = (const int*)d_in[3];
    float* out = (float*)d_out;

    cvt_kernel<<<BATCH * 64, NT>>>(K, V);
    meanv_final<<<BATCH, DIM>>>();

    cudaFuncSetAttribute(attn_kernel, cudaFuncAttributeMaxDynamicSharedMemorySize, SMEM_BYTES);
    attn_kernel<<<GRID, NT, SMEM_BYTES>>>(Q, vl, out);
}